// round 4
// baseline (speedup 1.0000x reference)
#include <cuda_runtime.h>
#include <cstdint>
#include <cstddef>

#define B_ROWS 8192
#define KDIM   4096
#define NMAX   4096
#define RCHUNK 32
#define ROWS_PER_CHUNK (B_ROWS / RCHUNK)   // 256

// GEMM tiling
#define BK          64
#define NSTAGES     4
#define STAGE_BYTES (2 * 128 * BK)          // A tile 8KB + B tile 8KB = 16KB
#define SMEM_GEMM   (NSTAGES * STAGE_BYTES) // 64 KB

// ---------------- scratch (device globals; no runtime allocation) ----------------
__device__ __align__(128) int8_t g_A0[(size_t)B_ROWS * KDIM];   // 33.5 MB
__device__ __align__(128) int8_t g_A1[(size_t)B_ROWS * KDIM];   // 33.5 MB
__device__ __align__(128) int8_t g_Wq[(size_t)NMAX  * KDIM];    // 16.8 MB (transposed [N][K])
__device__ int        g_S [(size_t)B_ROWS * NMAX];              // 134 MB
__device__ long long  g_psum  [RCHUNK * NMAX];
__device__ long long  g_psumsq[RCHUNK * NMAX];
__device__ int        g_pmax  [RCHUNK * NMAX];
__device__ int        g_pmin  [RCHUNK * NMAX];
__device__ float      g_mu[NMAX];
__device__ float      g_scale[NMAX];
__device__ float      g_amax[NMAX];
__device__ float      g_pexp[RCHUNK * 1024];
__device__ float      g_dinv[1024];

// ---------------- PTX helpers (base-target ISA only: sm_80-era) ----------------
__device__ __forceinline__ uint32_t smem_u32(const void* p) {
    uint32_t a;
    asm("{ .reg .u64 t; cvta.to.shared.u64 t, %1; cvt.u32.u64 %0, t; }" : "=r"(a) : "l"(p));
    return a;
}
__device__ __forceinline__ void cp_async16(uint32_t dst, const void* src) {
    asm volatile("cp.async.cg.shared.global [%0], [%1], 16;" :: "r"(dst), "l"(src) : "memory");
}
__device__ __forceinline__ void cp_commit() {
    asm volatile("cp.async.commit_group;" ::: "memory");
}
template <int N_> __device__ __forceinline__ void cp_wait() {
    asm volatile("cp.async.wait_group %0;" :: "n"(N_) : "memory");
}
__device__ __forceinline__ void ldsm4(uint32_t& r0, uint32_t& r1, uint32_t& r2, uint32_t& r3,
                                      uint32_t addr) {
    asm volatile("ldmatrix.sync.aligned.m8n8.x4.shared.b16 {%0,%1,%2,%3}, [%4];"
                 : "=r"(r0), "=r"(r1), "=r"(r2), "=r"(r3) : "r"(addr));
}
__device__ __forceinline__ void imma16832(int* c, const uint32_t* a, const uint32_t* b) {
    asm volatile(
        "mma.sync.aligned.m16n8k32.row.col.s32.s8.s8.s32 "
        "{%0,%1,%2,%3}, {%4,%5,%6,%7}, {%8,%9}, {%0,%1,%2,%3};"
        : "+r"(c[0]), "+r"(c[1]), "+r"(c[2]), "+r"(c[3])
        : "r"(a[0]), "r"(a[1]), "r"(a[2]), "r"(a[3]), "r"(b[0]), "r"(b[1]));
}

// ---------------- 1) x -> int8 +-1 ----------------
__global__ void convert_x_kernel(const float* __restrict__ x) {
    unsigned idx = blockIdx.x * 256u + threadIdx.x;       // over B*K/4
    float4 v = ((const float4*)x)[idx];
    char4 o;
    o.x = (v.x >= 0.5f) ? 1 : -1;
    o.y = (v.y >= 0.5f) ? 1 : -1;
    o.z = (v.z >= 0.5f) ? 1 : -1;
    o.w = (v.w >= 0.5f) ? 1 : -1;
    ((char4*)g_A0)[idx] = o;
}

// ---------------- 2) W[K][N] -> Wq[N][K] int8 +-1 (tiled transpose) ----------------
__global__ void convert_w_kernel(const float* __restrict__ W, int N) {
    __shared__ char t[32][33];
    int k0 = blockIdx.x * 32, n0 = blockIdx.y * 32;
    int tx = threadIdx.x, ty = threadIdx.y;
    #pragma unroll
    for (int i = 0; i < 4; ++i) {
        int r = ty + i * 8;                               // local k
        t[r][tx] = (W[(size_t)(k0 + r) * N + n0 + tx] >= 0.0f) ? 1 : -1;
    }
    __syncthreads();
    #pragma unroll
    for (int i = 0; i < 4; ++i) {
        int r = ty + i * 8;                               // local n
        g_Wq[(size_t)(n0 + r) * KDIM + k0 + tx] = t[tx][r];
    }
}

// ---------------- 3) s8 IMMA GEMM: S[i][j] = sum_k A[i][k] * Wq[j][k]  (exact s32) ----------------
// smem chunk swizzle: 64B row, 16B chunk c stored at c ^ ((row>>1)&3)  -> conflict-free LDSM/STS
__global__ __launch_bounds__(256, 2)
void gemm_imma_kernel(const int8_t* __restrict__ A, const int8_t* __restrict__ Bt, int N) {
    extern __shared__ __align__(128) char smem[];
    uint32_t sb = smem_u32(smem);
    int tid = threadIdx.x, wid = tid >> 5, lane = tid & 31;
    int rowBlk = blockIdx.y * 128, colBlk = blockIdx.x * 128;
    int wm = (wid & 1) * 64;                              // M band
    int wn = (wid >> 1) * 32;                             // N band

    // cp.async mapping: thread -> (row pair, 16B chunk)
    int cr = tid >> 2;                                    // 0..63
    int cc = tid & 3;                                     // chunk 0..3

    int acc[4][4][4];
    #pragma unroll
    for (int mt = 0; mt < 4; ++mt)
        #pragma unroll
        for (int nt = 0; nt < 4; ++nt)
            #pragma unroll
            for (int q = 0; q < 4; ++q) acc[mt][nt][q] = 0;

    const int NK = KDIM / BK;                             // 64

    // ldmatrix lane address offsets (within a stage's A / B tile)
    // A: x4 covers (rows 0-7,k0-15)(rows 8-15,k0-15)(rows 0-7,k16-31)(rows 8-15,k16-31)
    int a_row[4], a_sw[4];
    #pragma unroll
    for (int mt = 0; mt < 4; ++mt) {
        int r = wm + mt * 16 + (lane & 15);
        a_row[mt] = r * 64;
        a_sw[mt]  = (r >> 1) & 3;
    }
    int a_kc = lane >> 4;                                 // 0/1 = k half
    // B: x4 covers (n 0-7,k0-15)(n 0-7,k16-31)(n 8-15,k0-15)(n 8-15,k16-31)
    int b_row[2], b_sw[2];
    #pragma unroll
    for (int p = 0; p < 2; ++p) {
        int r = wn + p * 16 + ((lane >> 4) & 1) * 8 + (lane & 7);
        b_row[p] = r * 64;
        b_sw[p]  = (r >> 1) & 3;
    }
    int b_kc = (lane >> 3) & 1;

    // stage issue: 2 A chunks + 2 B chunks per thread
    auto issue = [&](int s, int kb) {
        uint32_t base = sb + s * STAGE_BYTES;
        size_t gk = (size_t)kb * BK + cc * 16;
        #pragma unroll
        for (int h = 0; h < 2; ++h) {
            int r = cr + h * 64;
            uint32_t sw = (uint32_t)(cc ^ ((r >> 1) & 3)) * 16;
            cp_async16(base + r * 64 + sw,          A  + (size_t)(rowBlk + r) * KDIM + gk);
            cp_async16(base + 8192 + r * 64 + sw,   Bt + (size_t)(colBlk + r) * KDIM + gk);
        }
    };

    issue(0, 0); cp_commit();
    issue(1, 1); cp_commit();
    issue(2, 2); cp_commit();

    for (int i = 0; i < NK; ++i) {
        int s = i & (NSTAGES - 1);
        cp_wait<2>();
        __syncthreads();
        uint32_t aBase = sb + s * STAGE_BYTES;
        uint32_t bBase = aBase + 8192;
        #pragma unroll
        for (int ks = 0; ks < 2; ++ks) {
            uint32_t af[4][4], bf[2][4];
            #pragma unroll
            for (int mt = 0; mt < 4; ++mt) {
                uint32_t addr = aBase + a_row[mt] + (uint32_t)(((ks * 2 + a_kc) ^ a_sw[mt]) * 16);
                ldsm4(af[mt][0], af[mt][1], af[mt][2], af[mt][3], addr);
            }
            #pragma unroll
            for (int p = 0; p < 2; ++p) {
                uint32_t addr = bBase + b_row[p] + (uint32_t)(((ks * 2 + b_kc) ^ b_sw[p]) * 16);
                ldsm4(bf[p][0], bf[p][1], bf[p][2], bf[p][3], addr);
            }
            #pragma unroll
            for (int mt = 0; mt < 4; ++mt)
                #pragma unroll
                for (int nt = 0; nt < 4; ++nt)
                    imma16832(acc[mt][nt], af[mt], &bf[nt >> 1][(nt & 1) * 2]);
        }
        if (i + 3 < NK) issue((i + 3) & (NSTAGES - 1), i + 3);
        cp_commit();
    }

    // epilogue: write s32 accumulators
    int g = lane >> 2, tg = lane & 3;
    #pragma unroll
    for (int mt = 0; mt < 4; ++mt) {
        int row0 = rowBlk + wm + mt * 16 + g;
        #pragma unroll
        for (int nt = 0; nt < 4; ++nt) {
            int col = colBlk + wn + nt * 8 + tg * 2;
            *(int2*)&g_S[(size_t)row0 * N + col]       = make_int2(acc[mt][nt][0], acc[mt][nt][1]);
            *(int2*)&g_S[(size_t)(row0 + 8) * N + col] = make_int2(acc[mt][nt][2], acc[mt][nt][3]);
        }
    }
}

// ---------------- 4) per-column partial stats ----------------
__global__ void colstats_kernel(int N) {
    int j = blockIdx.x * 256 + threadIdx.x;
    int c = blockIdx.y;
    const int* p = g_S + (size_t)c * ROWS_PER_CHUNK * N + j;
    long long sum = 0, ss = 0;
    int mx = -2147483647, mn = 2147483647;
    #pragma unroll 8
    for (int r = 0; r < ROWS_PER_CHUNK; ++r) {
        int v = p[(size_t)r * N];
        sum += v; ss += (long long)(v * v);
        mx = max(mx, v); mn = min(mn, v);
    }
    g_psum[c * N + j] = sum; g_psumsq[c * N + j] = ss;
    g_pmax[c * N + j] = mx;  g_pmin[c * N + j] = mn;
}

// ---------------- 5) finalize mu/scale/amax ----------------
__global__ void finalize_stats_kernel(const float* __restrict__ gamma,
                                      const float* __restrict__ beta,
                                      int layer, int N) {
    int j = blockIdx.x * 256 + threadIdx.x;
    long long sum = 0, ss = 0;
    int mx = -2147483647, mn = 2147483647;
    #pragma unroll
    for (int c = 0; c < RCHUNK; ++c) {
        sum += g_psum[c * N + j]; ss += g_psumsq[c * N + j];
        mx = max(mx, g_pmax[c * N + j]); mn = min(mn, g_pmin[c * N + j]);
    }
    double m   = (double)sum / (double)B_ROWS;
    double var = (double)ss  / (double)B_ROWS - m * m;
    float sc = gamma[layer] * rsqrtf((float)var + 1e-5f);
    float be = beta[layer];
    g_mu[j] = (float)m; g_scale[j] = sc;
    float hi = ((float)mx - (float)m) * sc + be;
    float lo = ((float)mn - (float)m) * sc + be;
    g_amax[j] = fmaxf(hi, lo);
}

// ---------------- 6) BN + binarize -> int8 +-1 activations ----------------
__global__ void bn_bin_kernel(const float* __restrict__ beta, int layer,
                              int8_t* __restrict__ out, int N) {
    unsigned idx = blockIdx.x * 256u + threadIdx.x;       // over B*N (exact)
    int j = idx & (unsigned)(N - 1);
    float a = ((float)g_S[idx] - g_mu[j]) * g_scale[j] + beta[layer];
    out[idx] = (a >= 0.0f) ? 1 : -1;
}

// ---------------- 7) softmax over batch ----------------
__global__ void sumexp_kernel(const float* __restrict__ beta, int N) {
    int j = blockIdx.x * 256 + threadIdx.x;
    int c = blockIdx.y;
    float m = g_mu[j], sc = g_scale[j], be = beta[2], ax = g_amax[j];
    const int* p = g_S + (size_t)c * ROWS_PER_CHUNK * N + j;
    float sum = 0.0f;
    #pragma unroll 8
    for (int r = 0; r < ROWS_PER_CHUNK; ++r)
        sum += __expf(((float)p[(size_t)r * N] - m) * sc + be - ax);
    g_pexp[c * N + j] = sum;
}
__global__ void finalize_denom_kernel(int N) {
    int j = blockIdx.x * 256 + threadIdx.x;
    float s = 0.0f;
    #pragma unroll
    for (int c = 0; c < RCHUNK; ++c) s += g_pexp[c * N + j];
    g_dinv[j] = 1.0f / s;
}
__global__ void write_out_kernel(const float* __restrict__ beta,
                                 float* __restrict__ out, int N) {
    unsigned idx = blockIdx.x * 256u + threadIdx.x;
    int j = idx & (unsigned)(N - 1);
    float a = ((float)g_S[idx] - g_mu[j]) * g_scale[j] + beta[2] - g_amax[j];
    out[idx] = __expf(a) * g_dinv[j];
}

// ---------------- driver ----------------
extern "C" void kernel_launch(void* const* d_in, const int* in_sizes, int n_in,
                              void* d_out, int out_size) {
    (void)in_sizes; (void)n_in; (void)out_size;
    const float* x     = (const float*)d_in[0];
    const float* Ws[3] = {(const float*)d_in[1], (const float*)d_in[2], (const float*)d_in[3]};
    const float* gamma = (const float*)d_in[4];
    const float* beta  = (const float*)d_in[5];
    float* out = (float*)d_out;
    const int Ns[3] = {4096, 4096, 1024};

    int8_t *aBuf[2], *wBuf;
    cudaGetSymbolAddress((void**)&aBuf[0], g_A0);
    cudaGetSymbolAddress((void**)&aBuf[1], g_A1);
    cudaGetSymbolAddress((void**)&wBuf,    g_Wq);

    cudaFuncSetAttribute(gemm_imma_kernel, cudaFuncAttributeMaxDynamicSharedMemorySize, SMEM_GEMM);

    convert_x_kernel<<<(B_ROWS * KDIM / 4) / 256, 256>>>(x);

    int cur = 0;
    for (int k = 0; k < 3; ++k) {
        int N = Ns[k];
        convert_w_kernel<<<dim3(KDIM / 32, N / 32), dim3(32, 8)>>>(Ws[k], N);

        gemm_imma_kernel<<<dim3(N / 128, B_ROWS / 128), 256, SMEM_GEMM>>>(aBuf[cur], wBuf, N);

        colstats_kernel<<<dim3(N / 256, RCHUNK), 256>>>(N);
        finalize_stats_kernel<<<N / 256, 256>>>(gamma, beta, k, N);
        if (k < 2) {
            bn_bin_kernel<<<(B_ROWS * N) / 256, 256>>>(beta, k, aBuf[cur ^ 1], N);
            cur ^= 1;
        } else {
            sumexp_kernel<<<dim3(N / 256, RCHUNK), 256>>>(beta, N);
            finalize_denom_kernel<<<N / 256, 256>>>(N);
            write_out_kernel<<<(B_ROWS * N) / 256, 256>>>(beta, out, N);
        }
    }
}

// round 8
// speedup vs baseline: 2.5964x; 2.5964x over previous
#include <cuda_runtime.h>
#include <cstdint>
#include <cstddef>

#define B_ROWS 8192
#define KDIM   4096
#define KW     128              // 4096 bits / 32
#define NMAX   4096
#define RCHUNK 32
#define ROWS_PER_CHUNK (B_ROWS / RCHUNK)   // 256

#define TILE       128
#define SROW       129                      // padded row stride (words) in smem
#define SMEM_GEMM  (2 * TILE * SROW * 4)    // 132096 bytes

// ---------------- scratch (device globals; no runtime allocation) ----------------
__device__ unsigned   g_A0[(size_t)B_ROWS * KW];        // 4 MB  packed activations ping
__device__ unsigned   g_A1[(size_t)B_ROWS * KW];        // 4 MB  packed activations pong
__device__ unsigned   g_Wb[(size_t)NMAX * KW];          // 2 MB  packed weights (per layer)
__device__ int        g_S [(size_t)B_ROWS * NMAX];      // 134 MB pre-BN integer activations
__device__ long long  g_psum  [RCHUNK * NMAX];
__device__ long long  g_psumsq[RCHUNK * NMAX];
__device__ int        g_pmax  [RCHUNK * NMAX];
__device__ int        g_pmin  [RCHUNK * NMAX];
__device__ float      g_mu[NMAX];
__device__ float      g_scale[NMAX];
__device__ float      g_amax[NMAX];
__device__ float      g_pexp[RCHUNK * 1024];
__device__ float      g_dinv[1024];

template<int IMM>
__device__ __forceinline__ unsigned lop3(unsigned a, unsigned b, unsigned c) {
    unsigned r;
    asm("lop3.b32 %0, %1, %2, %3, %4;" : "=r"(r) : "r"(a), "r"(b), "r"(c), "n"(IMM));
    return r;
}

// ---------------- 1) binarize+pack x ----------------
__global__ void pack_x_kernel(const float* __restrict__ x) {
    unsigned idx = blockIdx.x * 256u + threadIdx.x;          // over B*K (exact)
    float v = x[idx];
    unsigned m = __ballot_sync(0xFFFFFFFFu, (v - 0.5f) >= 0.0f);
    if ((threadIdx.x & 31u) == 0u) g_A0[idx >> 5] = m;
}

// ---------------- 2) binarize+pack W, column-major bits: g_Wb[j][w] ----------------
__global__ void pack_w_kernel(const float* __restrict__ W, int N) {
    int j = blockIdx.x * 256 + threadIdx.x;                  // output column
    int w = blockIdx.y;                                      // k-word 0..127
    const float* p = W + (size_t)w * 32 * N + j;
    unsigned m = 0;
    #pragma unroll
    for (int b = 0; b < 32; ++b)
        if (p[(size_t)b * N] >= 0.0f) m |= (1u << b);
    g_Wb[(size_t)j * KW + w] = m;
}

// ---------------- 3) XNOR GEMM with 7:3 carry-save popcount compression ----------------
// smem layout [word][row] (row stride 129 words); thread rows strided by 16 -> conflict-free LDS.
__global__ __launch_bounds__(256, 1)
void gemm_popc7_kernel(int which_a, int N) {
    const unsigned* __restrict__ A = which_a ? g_A1 : g_A0;
    extern __shared__ unsigned sm[];
    unsigned* sA = sm;
    unsigned* sB = sm + TILE * SROW;

    int tid = threadIdx.x, wid = tid >> 5, lane = tid & 31;
    int tx = tid & 15, ty = tid >> 4;
    int rowBlk = blockIdx.y * TILE, colBlk = blockIdx.x * TILE;

    // one-shot load + transpose into [word][row]
    #pragma unroll
    for (int p = 0; p < 16; ++p) {
        int row = p * 8 + wid;
        uint4 va = *(const uint4*)(A    + (size_t)(rowBlk + row) * KW + lane * 4);
        uint4 vb = *(const uint4*)(g_Wb + (size_t)(colBlk + row) * KW + lane * 4);
        sA[(lane * 4 + 0) * SROW + row] = va.x;
        sA[(lane * 4 + 1) * SROW + row] = va.y;
        sA[(lane * 4 + 2) * SROW + row] = va.z;
        sA[(lane * 4 + 3) * SROW + row] = va.w;
        sB[(lane * 4 + 0) * SROW + row] = vb.x;
        sB[(lane * 4 + 1) * SROW + row] = vb.y;
        sB[(lane * 4 + 2) * SROW + row] = vb.z;
        sB[(lane * 4 + 3) * SROW + row] = vb.w;
    }
    __syncthreads();

    int acc[8][8];                                            // weighted mismatch counts
    #pragma unroll
    for (int m = 0; m < 8; ++m)
        #pragma unroll
        for (int n = 0; n < 8; ++n) acc[m][n] = 0;

    unsigned aF[8][7];
    for (int g = 0; g < 18; ++g) {                            // 18 groups of 7 words
        int w0 = g * 7;
        #pragma unroll
        for (int mt = 0; mt < 8; ++mt)
            #pragma unroll
            for (int i = 0; i < 7; ++i)
                aF[mt][i] = sA[(w0 + i) * SROW + ty + 16 * mt];
        #pragma unroll
        for (int nt = 0; nt < 8; ++nt) {
            unsigned b[7];
            #pragma unroll
            for (int i = 0; i < 7; ++i)
                b[i] = sB[(w0 + i) * SROW + tx + 16 * nt];
            #pragma unroll
            for (int mt = 0; mt < 8; ++mt) {
                unsigned x0 = aF[mt][0] ^ b[0], x1 = aF[mt][1] ^ b[1];
                unsigned x2 = aF[mt][2] ^ b[2], x3 = aF[mt][3] ^ b[3];
                unsigned x4 = aF[mt][4] ^ b[4], x5 = aF[mt][5] ^ b[5];
                unsigned x6 = aF[mt][6] ^ b[6];
                unsigned s0 = lop3<0x96>(x0, x1, x2), c0 = lop3<0xE8>(x0, x1, x2);
                unsigned s1 = lop3<0x96>(x3, x4, x5), c1 = lop3<0xE8>(x3, x4, x5);
                unsigned s2 = lop3<0x96>(s0, s1, x6), c2 = lop3<0xE8>(s0, s1, x6);
                unsigned s3 = lop3<0x96>(c0, c1, c2), c3 = lop3<0xE8>(c0, c1, c2);
                acc[mt][nt] += __popc(s2) + 2 * __popc(s3) + 4 * __popc(c3);
            }
        }
    }
    // leftover words 126, 127 (weight-1 direct popcounts)
    {
        unsigned aL[8][2];
        #pragma unroll
        for (int mt = 0; mt < 8; ++mt) {
            aL[mt][0] = sA[126 * SROW + ty + 16 * mt];
            aL[mt][1] = sA[127 * SROW + ty + 16 * mt];
        }
        #pragma unroll
        for (int nt = 0; nt < 8; ++nt) {
            unsigned b0 = sB[126 * SROW + tx + 16 * nt];
            unsigned b1 = sB[127 * SROW + tx + 16 * nt];
            #pragma unroll
            for (int mt = 0; mt < 8; ++mt)
                acc[mt][nt] += __popc(aL[mt][0] ^ b0) + __popc(aL[mt][1] ^ b1);
        }
    }

    #pragma unroll
    for (int mt = 0; mt < 8; ++mt) {
        int row = rowBlk + ty + 16 * mt;
        #pragma unroll
        for (int nt = 0; nt < 8; ++nt) {
            int col = colBlk + tx + 16 * nt;
            g_S[(size_t)row * N + col] = KDIM - 2 * acc[mt][nt];
        }
    }
}

// ---------------- 4) per-column partial stats ----------------
__global__ void colstats_kernel(int N) {
    int j = blockIdx.x * 256 + threadIdx.x;
    int c = blockIdx.y;
    const int* p = g_S + (size_t)c * ROWS_PER_CHUNK * N + j;
    long long sum = 0, ss = 0;
    int mx = -2147483647, mn = 2147483647;
    #pragma unroll 8
    for (int r = 0; r < ROWS_PER_CHUNK; ++r) {
        int v = p[(size_t)r * N];
        sum += v; ss += (long long)(v * v);
        mx = max(mx, v); mn = min(mn, v);
    }
    g_psum[c * N + j] = sum; g_psumsq[c * N + j] = ss;
    g_pmax[c * N + j] = mx;  g_pmin[c * N + j] = mn;
}

// ---------------- 5) finalize mu/scale/amax ----------------
__global__ void finalize_stats_kernel(const float* __restrict__ gamma,
                                      const float* __restrict__ beta,
                                      int layer, int N) {
    int j = blockIdx.x * 256 + threadIdx.x;
    long long sum = 0, ss = 0;
    int mx = -2147483647, mn = 2147483647;
    #pragma unroll
    for (int c = 0; c < RCHUNK; ++c) {
        sum += g_psum[c * N + j]; ss += g_psumsq[c * N + j];
        mx = max(mx, g_pmax[c * N + j]); mn = min(mn, g_pmin[c * N + j]);
    }
    double m   = (double)sum / (double)B_ROWS;
    double var = (double)ss  / (double)B_ROWS - m * m;
    float sc = gamma[layer] * rsqrtf((float)var + 1e-5f);
    float be = beta[layer];
    g_mu[j] = (float)m; g_scale[j] = sc;
    float hi = ((float)mx - (float)m) * sc + be;
    float lo = ((float)mn - (float)m) * sc + be;
    g_amax[j] = fmaxf(hi, lo);
}

// ---------------- 6) BN + binarize + repack ----------------
__global__ void bn_bin_pack_kernel(const float* __restrict__ beta,
                                   int layer, int which_out, int N) {
    unsigned idx = blockIdx.x * 256u + threadIdx.x;          // over B*N (exact)
    int j = idx & (unsigned)(N - 1);
    float a = ((float)g_S[idx] - g_mu[j]) * g_scale[j] + beta[layer];
    unsigned m = __ballot_sync(0xFFFFFFFFu, a >= 0.0f);
    unsigned* out = which_out ? g_A1 : g_A0;
    if ((threadIdx.x & 31u) == 0u) out[idx >> 5] = m;
}

// ---------------- 7) softmax over batch ----------------
__global__ void sumexp_kernel(const float* __restrict__ beta, int N) {
    int j = blockIdx.x * 256 + threadIdx.x;
    int c = blockIdx.y;
    float m = g_mu[j], sc = g_scale[j], be = beta[2], ax = g_amax[j];
    const int* p = g_S + (size_t)c * ROWS_PER_CHUNK * N + j;
    float sum = 0.0f;
    #pragma unroll 8
    for (int r = 0; r < ROWS_PER_CHUNK; ++r)
        sum += __expf(((float)p[(size_t)r * N] - m) * sc + be - ax);
    g_pexp[c * N + j] = sum;
}
__global__ void finalize_denom_kernel(int N) {
    int j = blockIdx.x * 256 + threadIdx.x;
    float s = 0.0f;
    #pragma unroll
    for (int c = 0; c < RCHUNK; ++c) s += g_pexp[c * N + j];
    g_dinv[j] = 1.0f / s;
}
__global__ void write_out_kernel(const float* __restrict__ beta,
                                 float* __restrict__ out, int N) {
    unsigned idx = blockIdx.x * 256u + threadIdx.x;
    int j = idx & (unsigned)(N - 1);
    float a = ((float)g_S[idx] - g_mu[j]) * g_scale[j] + beta[2] - g_amax[j];
    out[idx] = __expf(a) * g_dinv[j];
}

// ---------------- driver ----------------
extern "C" void kernel_launch(void* const* d_in, const int* in_sizes, int n_in,
                              void* d_out, int out_size) {
    (void)in_sizes; (void)n_in; (void)out_size;
    const float* x     = (const float*)d_in[0];
    const float* Ws[3] = {(const float*)d_in[1], (const float*)d_in[2], (const float*)d_in[3]};
    const float* gamma = (const float*)d_in[4];
    const float* beta  = (const float*)d_in[5];
    float* out = (float*)d_out;
    const int Ns[3] = {4096, 4096, 1024};

    cudaFuncSetAttribute(gemm_popc7_kernel, cudaFuncAttributeMaxDynamicSharedMemorySize, SMEM_GEMM);

    pack_x_kernel<<<(B_ROWS * KDIM) / 256, 256>>>(x);

    int cur = 0;
    for (int k = 0; k < 3; ++k) {
        int N = Ns[k];
        pack_w_kernel<<<dim3(N / 256, KW), 256>>>(Ws[k], N);
        gemm_popc7_kernel<<<dim3(N / TILE, B_ROWS / TILE), 256, SMEM_GEMM>>>(cur, N);
        colstats_kernel<<<dim3(N / 256, RCHUNK), 256>>>(N);
        finalize_stats_kernel<<<N / 256, 256>>>(gamma, beta, k, N);
        if (k < 2) {
            bn_bin_pack_kernel<<<(B_ROWS * N) / 256, 256>>>(beta, k, cur ^ 1, N);
            cur ^= 1;
        } else {
            sumexp_kernel<<<dim3(N / 256, RCHUNK), 256>>>(beta, N);
            finalize_denom_kernel<<<N / 256, 256>>>(N);
            write_out_kernel<<<(B_ROWS * N) / 256, 256>>>(beta, out, N);
        }
    }
}